// round 2
// baseline (speedup 1.0000x reference)
#include <cuda_runtime.h>
#include <math.h>

#define BB 32
#define MM 60
#define NN 8400
#define CC 80
#define INF_COST 1e8f
#define FULL 0xFFFFFFFFu

// Scratch (device globals: allocation-free)
__device__ float g_cost[(size_t)BB * MM * NN];               // [b][m][n]
__device__ float g_iou [(size_t)BB * MM * NN];               // [b][m][n]
__device__ unsigned long long g_mask[(size_t)BB * NN];       // per-prior GT bitmask
__device__ unsigned char g_valid[(size_t)BB * NN];

__device__ __forceinline__ unsigned int f2o(float f) {
    unsigned int u = __float_as_uint(f);
    return (u & 0x80000000u) ? ~u : (u | 0x80000000u);  // monotonic float->uint
}

// Pass A: valid_mask per (b, n); zero matching masks.
__global__ void k_valid(const float* __restrict__ priors,
                        const float* __restrict__ gt_bboxes,
                        const float* __restrict__ pad_flag) {
    int idx = blockIdx.x * blockDim.x + threadIdx.x;
    if (idx >= BB * NN) return;
    int b = idx / NN, n = idx % NN;
    float px = priors[n * 4 + 0], py = priors[n * 4 + 1];
    const float* gb = gt_bboxes + (size_t)b * MM * 4;
    const float* pf = pad_flag + (size_t)b * MM;
    bool any = false;
    for (int m = 0; m < MM; m++) {
        float x1 = gb[m * 4 + 0], y1 = gb[m * 4 + 1];
        float x2 = gb[m * 4 + 2], y2 = gb[m * 4 + 3];
        float mn = fminf(fminf(px - x1, py - y1), fminf(x2 - px, y2 - py));
        if (mn > 0.f && pf[m] > 0.f) any = true;
    }
    g_valid[idx] = any ? 1 : 0;
    g_mask[idx] = 0ull;
}

// Pass B (fused): per (b,m) block computes its cost/iou column into smem +
// global, then (valid GTs only) warp-local top-k selection + merge.
__global__ void __launch_bounds__(256) k_fused(
        const float* __restrict__ pred_bboxes,
        const float* __restrict__ pred_scores,
        const float* __restrict__ priors,
        const int* __restrict__ gt_labels,
        const float* __restrict__ gt_bboxes,
        const float* __restrict__ pad_flag) {
    int bm = blockIdx.x;
    int b = bm / MM, m = bm % MM;
    int tid = threadIdx.x;
    int lane = tid & 31, wid = tid >> 5;

    extern __shared__ float sh[];
    float* s_iou  = sh;
    float* s_cost = sh + NN;
    __shared__ unsigned long long s_cand[8 * 13];
    __shared__ int s_ks;

    const float* gb = gt_bboxes + (size_t)bm * 4;
    float gx1 = gb[0], gy1 = gb[1], gx2 = gb[2], gy2 = gb[3];
    int label = gt_labels[bm];
    float cx = 0.5f * (gx1 + gx2), cy = 0.5f * (gy1 + gy2);
    float a2 = (gx2 - gx1) * (gy2 - gy1);

    const float4* pbb = (const float4*)pred_bboxes + (size_t)b * NN;
    const float4* prr = (const float4*)priors;
    const float* scb = pred_scores + (size_t)b * NN * CC + label;
    const unsigned char* vld = g_valid + (size_t)b * NN;
    float* gC = g_cost + (size_t)bm * NN;
    float* gI = g_iou  + (size_t)bm * NN;

    for (int n = tid; n < NN; n += 256) {
        float4 pb = pbb[n];
        float lx = fmaxf(pb.x, gx1), ly = fmaxf(pb.y, gy1);
        float rx = fminf(pb.z, gx2), ry = fminf(pb.w, gy2);
        float iw = fmaxf(rx - lx, 0.f), ih = fmaxf(ry - ly, 0.f);
        float inter = iw * ih;
        float a1 = (pb.z - pb.x) * (pb.w - pb.y);
        float uni = fmaxf(a1 + a2 - inter, 1e-6f);
        float iou = inter / uni;
        s_iou[n] = iou; gI[n] = iou;

        float cost;
        if (!vld[n]) {
            cost = INF_COST;
        } else {
            float4 pr = prr[n];
            float dx = pr.x - cx, dy = pr.y - cy;
            float dist = sqrtf(dx * dx + dy * dy) / pr.z;
            float soft = exp10f(dist - 3.0f);
            float iou_cost = -logf(iou + 1e-7f) * 3.0f;
            float t = scb[(size_t)n * CC];
            float e = expf(-fabsf(t));
            float sig = (t >= 0.f) ? 1.f / (1.f + e) : e / (1.f + e);
            float bce = fmaxf(t, 0.f) - t * iou + log1pf(e);
            float sc = iou - sig;
            cost = bce * sc * sc + iou_cost + soft;
        }
        s_cost[n] = cost; gC[n] = cost;
    }
    if (pad_flag[bm] <= 0.f) return;   // padded GT: column written, no selection
    __syncthreads();

    // ---- Phase 1: top-13 iou keys per warp (cached max + removal bitmask) ----
    {
        unsigned long long used = 0ull, mykey = 0ull;
        int myj = 0;
        for (int j = 0, n = tid; n < NN; j++, n += 256) {
            unsigned long long k = ((unsigned long long)f2o(s_iou[n]) << 32) | (unsigned)n;
            if (k > mykey) { mykey = k; myj = j; }
        }
        for (int it = 0; it < 13; it++) {
            unsigned long long w = mykey;
            #pragma unroll
            for (int off = 16; off; off >>= 1) {
                unsigned long long o = __shfl_xor_sync(FULL, w, off);
                if (o > w) w = o;
            }
            if (mykey == w && w != 0ull) {
                used |= 1ull << myj;
                mykey = 0ull; myj = 0;
                for (int j = 0, n = tid; n < NN; j++, n += 256) {
                    if ((used >> j) & 1ull) continue;
                    unsigned long long k = ((unsigned long long)f2o(s_iou[n]) << 32) | (unsigned)n;
                    if (k > mykey) { mykey = k; myj = j; }
                }
            }
            if (lane == 0) s_cand[wid * 13 + it] = w;
        }
    }
    __syncthreads();

    // warp 0 merges 104 candidates -> dynamic_ks
    if (wid == 0) {
        unsigned long long c[4];
        #pragma unroll
        for (int r = 0; r < 4; r++) {
            int i = lane + 32 * r;
            c[r] = (i < 104) ? s_cand[i] : 0ull;
        }
        int used4 = 0;
        float sum = 0.f;
        for (int it = 0; it < 13; it++) {
            unsigned long long mk = 0ull; int mr = 0;
            #pragma unroll
            for (int r = 0; r < 4; r++)
                if (!((used4 >> r) & 1) && c[r] > mk) { mk = c[r]; mr = r; }
            unsigned long long w = mk;
            #pragma unroll
            for (int off = 16; off; off >>= 1) {
                unsigned long long o = __shfl_xor_sync(FULL, w, off);
                if (o > w) w = o;
            }
            if (mk == w && w != 0ull) used4 |= 1 << mr;
            sum += __uint_as_float((unsigned)(w >> 32) ^ 0x80000000u);
        }
        int ks = (int)sum;               // trunc toward 0, matches astype(int32)
        if (ks < 1) ks = 1;
        if (ks > 13) ks = 13;
        if (lane == 0) s_ks = ks;
    }
    __syncthreads();
    int ks = s_ks;

    // ---- Phase 2: bottom-ks cost keys per warp ----
    {
        unsigned long long used = 0ull, mykey = ~0ull;
        int myj = 0;
        for (int j = 0, n = tid; n < NN; j++, n += 256) {
            unsigned long long k = ((unsigned long long)f2o(s_cost[n]) << 32) | (unsigned)n;
            if (k < mykey) { mykey = k; myj = j; }
        }
        for (int it = 0; it < ks; it++) {
            unsigned long long w = mykey;
            #pragma unroll
            for (int off = 16; off; off >>= 1) {
                unsigned long long o = __shfl_xor_sync(FULL, w, off);
                if (o < w) w = o;
            }
            if (mykey == w && w != ~0ull) {
                used |= 1ull << myj;
                mykey = ~0ull; myj = 0;
                for (int j = 0, n = tid; n < NN; j++, n += 256) {
                    if ((used >> j) & 1ull) continue;
                    unsigned long long k = ((unsigned long long)f2o(s_cost[n]) << 32) | (unsigned)n;
                    if (k < mykey) { mykey = k; myj = j; }
                }
            }
            if (lane == 0) s_cand[wid * 13 + it] = w;
        }
    }
    __syncthreads();

    // warp 0 merges 8*ks candidates -> set bits for global bottom-ks
    if (wid == 0) {
        unsigned long long c[4];
        #pragma unroll
        for (int r = 0; r < 4; r++) {
            int i = lane + 32 * r;
            c[r] = (i < 104 && (i % 13) < ks) ? s_cand[i] : ~0ull;
        }
        int used4 = 0;
        for (int it = 0; it < ks; it++) {
            unsigned long long mk = ~0ull; int mr = 0;
            #pragma unroll
            for (int r = 0; r < 4; r++)
                if (!((used4 >> r) & 1) && c[r] < mk) { mk = c[r]; mr = r; }
            unsigned long long w = mk;
            #pragma unroll
            for (int off = 16; off; off >>= 1) {
                unsigned long long o = __shfl_xor_sync(FULL, w, off);
                if (o < w) w = o;
            }
            if (mk == w && w != ~0ull) used4 |= 1 << mr;
            if (lane == 0)
                atomicOr(&g_mask[(size_t)b * NN + (unsigned)(w & 0xFFFFFFFFu)], 1ull << m);
        }
    }
}

// Pass C: per (b, n) resolve multi-matches, emit all 4 outputs (float32 concat).
__global__ void k_out(const int* __restrict__ gt_labels,
                      const float* __restrict__ gt_bboxes,
                      float* __restrict__ out) {
    int idx = blockIdx.x * blockDim.x + threadIdx.x;
    if (idx >= BB * NN) return;
    int b = idx / NN, n = idx % NN;

    unsigned long long mask = g_mask[idx];
    if (__popcll(mask) > 1) {
        unsigned int bo = 0xFFFFFFFFu;
        int am = 0;
        for (int m = 0; m < MM; m++) {
            unsigned int o = f2o(g_cost[((size_t)b * MM + m) * NN + n]);
            if (o < bo) { bo = o; am = m; }
        }
        mask = 1ull << am;
    }
    bool fg = (mask != 0ull);
    int matched = fg ? (__ffsll((long long)mask) - 1) : 0;

    float lab = fg ? (float)gt_labels[b * MM + matched] : (float)CC;
    float metric = fg ? g_iou[((size_t)b * MM + matched) * NN + n] : 0.f;
    float4 bb = make_float4(0.f, 0.f, 0.f, 0.f);
    if (fg) bb = ((const float4*)gt_bboxes)[b * MM + matched];

    size_t S = (size_t)BB * NN;
    out[idx] = lab;
    out[S + idx] = 1.0f;
    ((float4*)(out + 2 * S))[idx] = bb;
    out[6 * S + idx] = metric;
}

extern "C" void kernel_launch(void* const* d_in, const int* in_sizes, int n_in,
                              void* d_out, int out_size) {
    const float* pred_bboxes = (const float*)d_in[0];
    const float* pred_scores = (const float*)d_in[1];
    const float* priors      = (const float*)d_in[2];
    const int*   gt_labels   = (const int*)d_in[3];
    const float* gt_bboxes   = (const float*)d_in[4];
    const float* pad_flag    = (const float*)d_in[5];
    float* out = (float*)d_out;

    k_valid<<<(BB * NN + 255) / 256, 256>>>(priors, gt_bboxes, pad_flag);

    size_t shbytes = 2 * (size_t)NN * sizeof(float);  // 67200 B
    static int attr_set = 0;
    if (!attr_set) {
        cudaFuncSetAttribute(k_fused, cudaFuncAttributeMaxDynamicSharedMemorySize, (int)shbytes);
        attr_set = 1;
    }
    k_fused<<<BB * MM, 256, shbytes>>>(pred_bboxes, pred_scores, priors,
                                       gt_labels, gt_bboxes, pad_flag);

    k_out<<<(BB * NN + 255) / 256, 256>>>(gt_labels, gt_bboxes, out);
}

// round 3
// speedup vs baseline: 1.2287x; 1.2287x over previous
#include <cuda_runtime.h>
#include <math.h>

#define BB 32
#define MM 60
#define NN 8400
#define CC 80
#define TILE 128
#define NTILES ((NN + TILE - 1) / TILE)   // 66
#define INF_COST 1e8f
#define FULL 0xFFFFFFFFu

// Scratch (device globals: allocation-free)
__device__ float g_cost[(size_t)BB * MM * NN];               // [b][m][n]
__device__ float g_iou [(size_t)BB * MM * NN];               // [b][m][n]
__device__ unsigned long long g_mask[(size_t)BB * NN];       // per-prior GT bitmask

__device__ __forceinline__ unsigned int f2o(float f) {
    unsigned int u = __float_as_uint(f);
    return (u & 0x80000000u) ? ~u : (u | 0x80000000u);  // monotonic float->uint
}

// Pass A: per (b, prior-tile) block. Stages score rows + GT data in smem,
// loops over m. Emits cost+iou transposed [b][m][n]; zeroes g_mask; computes
// valid inline.
__global__ void __launch_bounds__(TILE) k_cost(
        const float* __restrict__ pred_bboxes,
        const float* __restrict__ pred_scores,
        const float* __restrict__ priors,
        const int* __restrict__ gt_labels,
        const float* __restrict__ gt_bboxes,
        const float* __restrict__ pad_flag) {
    int b = blockIdx.y;
    int n0 = blockIdx.x * TILE;
    int tid = threadIdx.x;
    int n = n0 + tid;
    bool inb = (n < NN);

    __shared__ float  s_sc[TILE][CC + 1];     // +1 pad: stride 81, conflict-free
    __shared__ float4 s_gt[MM];
    __shared__ float  s_cx[MM], s_cy[MM], s_a2[MM], s_pf[MM];
    __shared__ int    s_lab[MM];

    if (tid < MM) {
        float4 g = ((const float4*)gt_bboxes)[b * MM + tid];
        s_gt[tid] = g;
        s_cx[tid] = 0.5f * (g.x + g.z);
        s_cy[tid] = 0.5f * (g.y + g.w);
        s_a2[tid] = (g.z - g.x) * (g.w - g.y);
        s_lab[tid] = gt_labels[b * MM + tid];
        s_pf[tid] = pad_flag[b * MM + tid];
    }
    // stage score rows (contiguous chunk, coalesced float4)
    {
        int rows = min(TILE, NN - n0);
        const float4* src = (const float4*)(pred_scores + ((size_t)b * NN + n0) * CC);
        int tot4 = rows * (CC / 4);
        for (int i = tid; i < tot4; i += TILE) {
            float4 v = src[i];
            int r = i / (CC / 4), c = (i % (CC / 4)) * 4;
            s_sc[r][c] = v.x; s_sc[r][c + 1] = v.y;
            s_sc[r][c + 2] = v.z; s_sc[r][c + 3] = v.w;
        }
    }
    __syncthreads();

    float4 pb = make_float4(0, 0, 0, 0), pr = make_float4(0, 0, 1, 1);
    if (inb) {
        pb = ((const float4*)pred_bboxes)[(size_t)b * NN + n];
        pr = ((const float4*)priors)[n];
        g_mask[(size_t)b * NN + n] = 0ull;
    }
    float a1 = (pb.z - pb.x) * (pb.w - pb.y);

    // valid_mask: prior center strictly inside any valid GT
    bool valid = false;
    #pragma unroll 4
    for (int m = 0; m < MM; m++) {
        float4 g = s_gt[m];
        float mn = fminf(fminf(pr.x - g.x, pr.y - g.y), fminf(g.z - pr.x, g.w - pr.y));
        if (mn > 0.f && s_pf[m] > 0.f) valid = true;
    }

    float* gC = g_cost + ((size_t)b * MM) * NN + n;
    float* gI = g_iou  + ((size_t)b * MM) * NN + n;

    for (int m = 0; m < MM; m++) {
        float4 g = s_gt[m];
        float lx = fmaxf(pb.x, g.x), ly = fmaxf(pb.y, g.y);
        float rx = fminf(pb.z, g.z), ry = fminf(pb.w, g.w);
        float iw = fmaxf(rx - lx, 0.f), ih = fmaxf(ry - ly, 0.f);
        float inter = iw * ih;
        float uni = fmaxf(a1 + s_a2[m] - inter, 1e-6f);
        float iou = inter / uni;

        float cost = INF_COST;
        if (valid) {
            float dx = pr.x - s_cx[m], dy = pr.y - s_cy[m];
            float dist = sqrtf(dx * dx + dy * dy) / pr.z;
            float soft = exp10f(dist - 3.0f);
            float iou_cost = -logf(iou + 1e-7f) * 3.0f;
            float t = s_sc[tid][s_lab[m]];
            float e = expf(-fabsf(t));
            float sig = (t >= 0.f) ? 1.f / (1.f + e) : e / (1.f + e);
            float bce = fmaxf(t, 0.f) - t * iou + log1pf(e);
            float sc = iou - sig;
            cost = bce * sc * sc + iou_cost + soft;
        }
        if (inb) {
            gI[(size_t)m * NN] = iou;
            gC[(size_t)m * NN] = cost;
        }
    }
}

// Pass B: per (b,m) valid GT: column -> smem, warp-local top-13 iou ->
// dynamic_ks, warp-local bottom-ks cost -> atomicOr bits.
__global__ void __launch_bounds__(256) k_match(const float* __restrict__ pad_flag) {
    int bm = blockIdx.x;
    int b = bm / MM, m = bm % MM;
    if (pad_flag[bm] <= 0.f) return;
    int tid = threadIdx.x;
    int lane = tid & 31, wid = tid >> 5;

    extern __shared__ float sh[];
    float* s_iou  = sh;
    float* s_cost = sh + NN;
    __shared__ unsigned long long s_cand[8 * 13];
    __shared__ int s_ks;

    const float* gC = g_cost + (size_t)bm * NN;
    const float* gI = g_iou  + (size_t)bm * NN;
    for (int n = tid; n < NN; n += 256) { s_iou[n] = gI[n]; s_cost[n] = gC[n]; }
    __syncthreads();

    // ---- Phase 1: top-13 iou keys per warp (cached max + consumed bitmask) ----
    {
        unsigned long long used = 0ull, mykey = 0ull;
        int myj = 0;
        for (int j = 0, n = tid; n < NN; j++, n += 256) {
            unsigned long long k = ((unsigned long long)f2o(s_iou[n]) << 32) | (unsigned)n;
            if (k > mykey) { mykey = k; myj = j; }
        }
        for (int it = 0; it < 13; it++) {
            unsigned long long w = mykey;
            #pragma unroll
            for (int off = 16; off; off >>= 1) {
                unsigned long long o = __shfl_xor_sync(FULL, w, off);
                if (o > w) w = o;
            }
            if (mykey == w && w != 0ull) {
                used |= 1ull << myj;
                mykey = 0ull; myj = 0;
                for (int j = 0, n = tid; n < NN; j++, n += 256) {
                    if ((used >> j) & 1ull) continue;
                    unsigned long long k = ((unsigned long long)f2o(s_iou[n]) << 32) | (unsigned)n;
                    if (k > mykey) { mykey = k; myj = j; }
                }
            }
            if (lane == 0) s_cand[wid * 13 + it] = w;
        }
    }
    __syncthreads();

    // warp 0 merges 8x13 candidates -> dynamic_ks
    if (wid == 0) {
        unsigned long long c[4];
        #pragma unroll
        for (int r = 0; r < 4; r++) {
            int i = lane + 32 * r;
            c[r] = (i < 104) ? s_cand[i] : 0ull;
        }
        int used4 = 0;
        float sum = 0.f;
        for (int it = 0; it < 13; it++) {
            unsigned long long mk = 0ull; int mr = 0;
            #pragma unroll
            for (int r = 0; r < 4; r++)
                if (!((used4 >> r) & 1) && c[r] > mk) { mk = c[r]; mr = r; }
            unsigned long long w = mk;
            #pragma unroll
            for (int off = 16; off; off >>= 1) {
                unsigned long long o = __shfl_xor_sync(FULL, w, off);
                if (o > w) w = o;
            }
            if (mk == w && w != 0ull) used4 |= 1 << mr;
            sum += __uint_as_float((unsigned)(w >> 32) ^ 0x80000000u);
        }
        int ks = (int)sum;               // trunc toward 0, matches astype(int32)
        if (ks < 1) ks = 1;
        if (ks > 13) ks = 13;
        if (lane == 0) s_ks = ks;
    }
    __syncthreads();
    int ks = s_ks;

    // ---- Phase 2: bottom-ks cost keys per warp ----
    {
        unsigned long long used = 0ull, mykey = ~0ull;
        int myj = 0;
        for (int j = 0, n = tid; n < NN; j++, n += 256) {
            unsigned long long k = ((unsigned long long)f2o(s_cost[n]) << 32) | (unsigned)n;
            if (k < mykey) { mykey = k; myj = j; }
        }
        for (int it = 0; it < ks; it++) {
            unsigned long long w = mykey;
            #pragma unroll
            for (int off = 16; off; off >>= 1) {
                unsigned long long o = __shfl_xor_sync(FULL, w, off);
                if (o < w) w = o;
            }
            if (mykey == w && w != ~0ull) {
                used |= 1ull << myj;
                mykey = ~0ull; myj = 0;
                for (int j = 0, n = tid; n < NN; j++, n += 256) {
                    if ((used >> j) & 1ull) continue;
                    unsigned long long k = ((unsigned long long)f2o(s_cost[n]) << 32) | (unsigned)n;
                    if (k < mykey) { mykey = k; myj = j; }
                }
            }
            if (lane == 0) s_cand[wid * 13 + it] = w;
        }
    }
    __syncthreads();

    // warp 0 merges 8*ks candidates -> set bit m for global bottom-ks priors
    if (wid == 0) {
        unsigned long long c[4];
        #pragma unroll
        for (int r = 0; r < 4; r++) {
            int i = lane + 32 * r;
            c[r] = (i < 104 && (i % 13) < ks) ? s_cand[i] : ~0ull;
        }
        int used4 = 0;
        for (int it = 0; it < ks; it++) {
            unsigned long long mk = ~0ull; int mr = 0;
            #pragma unroll
            for (int r = 0; r < 4; r++)
                if (!((used4 >> r) & 1) && c[r] < mk) { mk = c[r]; mr = r; }
            unsigned long long w = mk;
            #pragma unroll
            for (int off = 16; off; off >>= 1) {
                unsigned long long o = __shfl_xor_sync(FULL, w, off);
                if (o < w) w = o;
            }
            if (mk == w && w != ~0ull) used4 |= 1 << mr;
            if (lane == 0)
                atomicOr(&g_mask[(size_t)b * NN + (unsigned)(w & 0xFFFFFFFFu)], 1ull << m);
        }
    }
}

// Pass C: per (b, n) resolve multi-matches, emit all 4 outputs (float32 concat).
__global__ void k_out(const int* __restrict__ gt_labels,
                      const float* __restrict__ gt_bboxes,
                      float* __restrict__ out) {
    int idx = blockIdx.x * blockDim.x + threadIdx.x;
    if (idx >= BB * NN) return;
    int b = idx / NN, n = idx % NN;

    unsigned long long mask = g_mask[idx];
    if (__popcll(mask) > 1) {
        unsigned int bo = 0xFFFFFFFFu;
        int am = 0;
        for (int m = 0; m < MM; m++) {
            unsigned int o = f2o(g_cost[((size_t)b * MM + m) * NN + n]);
            if (o < bo) { bo = o; am = m; }
        }
        mask = 1ull << am;
    }
    bool fg = (mask != 0ull);
    int matched = fg ? (__ffsll((long long)mask) - 1) : 0;

    float lab = fg ? (float)gt_labels[b * MM + matched] : (float)CC;
    float metric = fg ? g_iou[((size_t)b * MM + matched) * NN + n] : 0.f;
    float4 bb = make_float4(0.f, 0.f, 0.f, 0.f);
    if (fg) bb = ((const float4*)gt_bboxes)[b * MM + matched];

    size_t S = (size_t)BB * NN;
    out[idx] = lab;
    out[S + idx] = 1.0f;
    ((float4*)(out + 2 * S))[idx] = bb;
    out[6 * S + idx] = metric;
}

extern "C" void kernel_launch(void* const* d_in, const int* in_sizes, int n_in,
                              void* d_out, int out_size) {
    const float* pred_bboxes = (const float*)d_in[0];
    const float* pred_scores = (const float*)d_in[1];
    const float* priors      = (const float*)d_in[2];
    const int*   gt_labels   = (const int*)d_in[3];
    const float* gt_bboxes   = (const float*)d_in[4];
    const float* pad_flag    = (const float*)d_in[5];
    float* out = (float*)d_out;

    dim3 gc(NTILES, BB);
    k_cost<<<gc, TILE>>>(pred_bboxes, pred_scores, priors,
                         gt_labels, gt_bboxes, pad_flag);

    size_t shbytes = 2 * (size_t)NN * sizeof(float);  // 67200 B
    static int attr_set = 0;
    if (!attr_set) {
        cudaFuncSetAttribute(k_match, cudaFuncAttributeMaxDynamicSharedMemorySize, (int)shbytes);
        attr_set = 1;
    }
    k_match<<<BB * MM, 256, shbytes>>>(pad_flag);

    k_out<<<(BB * NN + 255) / 256, 256>>>(gt_labels, gt_bboxes, out);
}

// round 4
// speedup vs baseline: 2.2638x; 1.8424x over previous
#include <cuda_runtime.h>
#include <math.h>

#define BB 32
#define MM 60
#define NN 8400
#define CC 80
#define TILE 128
#define NTILES ((NN + TILE - 1) / TILE)   // 66
#define JCNT 33                            // ceil(8400/256)
#define INF_COST 1e8f
#define FULL 0xFFFFFFFFu

// Scratch (device globals: allocation-free)
__device__ float g_cost[(size_t)BB * MM * NN];               // [b][m][n]
__device__ float g_iou [(size_t)BB * MM * NN];               // [b][m][n]
__device__ unsigned long long g_mask[(size_t)BB * NN];       // per-prior GT bitmask

__device__ __forceinline__ unsigned int f2o(float f) {
    unsigned int u = __float_as_uint(f);
    return (u & 0x80000000u) ? ~u : (u | 0x80000000u);  // monotonic float->uint
}

// Pass A: per (b, prior-tile) block. Stages score rows + GT data in smem,
// loops over m. Emits cost+iou transposed [b][m][n]; zeroes g_mask.
__global__ void __launch_bounds__(TILE) k_cost(
        const float* __restrict__ pred_bboxes,
        const float* __restrict__ pred_scores,
        const float* __restrict__ priors,
        const int* __restrict__ gt_labels,
        const float* __restrict__ gt_bboxes,
        const float* __restrict__ pad_flag) {
    int b = blockIdx.y;
    int n0 = blockIdx.x * TILE;
    int tid = threadIdx.x;
    int n = n0 + tid;
    bool inb = (n < NN);

    __shared__ float  s_sc[TILE][CC + 1];     // stride 81: conflict-free
    __shared__ float4 s_gt[MM];
    __shared__ float  s_cx[MM], s_cy[MM], s_a2[MM], s_pf[MM];
    __shared__ int    s_lab[MM];

    if (tid < MM) {
        float4 g = ((const float4*)gt_bboxes)[b * MM + tid];
        s_gt[tid] = g;
        s_cx[tid] = 0.5f * (g.x + g.z);
        s_cy[tid] = 0.5f * (g.y + g.w);
        s_a2[tid] = (g.z - g.x) * (g.w - g.y);
        s_lab[tid] = gt_labels[b * MM + tid];
        s_pf[tid] = pad_flag[b * MM + tid];
    }
    {
        int rows = min(TILE, NN - n0);
        const float4* src = (const float4*)(pred_scores + ((size_t)b * NN + n0) * CC);
        int tot4 = rows * (CC / 4);
        for (int i = tid; i < tot4; i += TILE) {
            float4 v = src[i];
            int r = i / (CC / 4), c = (i % (CC / 4)) * 4;
            s_sc[r][c] = v.x; s_sc[r][c + 1] = v.y;
            s_sc[r][c + 2] = v.z; s_sc[r][c + 3] = v.w;
        }
    }
    __syncthreads();

    float4 pb = make_float4(0, 0, 0, 0), pr = make_float4(0, 0, 1, 1);
    if (inb) {
        pb = ((const float4*)pred_bboxes)[(size_t)b * NN + n];
        pr = ((const float4*)priors)[n];
        g_mask[(size_t)b * NN + n] = 0ull;
    }
    float a1 = (pb.z - pb.x) * (pb.w - pb.y);
    float rstride = __frcp_rn(pr.z);

    bool valid = false;
    #pragma unroll 4
    for (int m = 0; m < MM; m++) {
        float4 g = s_gt[m];
        float mn = fminf(fminf(pr.x - g.x, pr.y - g.y), fminf(g.z - pr.x, g.w - pr.y));
        if (mn > 0.f && s_pf[m] > 0.f) valid = true;
    }

    float* gC = g_cost + ((size_t)b * MM) * NN + n;
    float* gI = g_iou  + ((size_t)b * MM) * NN + n;

    for (int m = 0; m < MM; m++) {
        float4 g = s_gt[m];
        float lx = fmaxf(pb.x, g.x), ly = fmaxf(pb.y, g.y);
        float rx = fminf(pb.z, g.z), ry = fminf(pb.w, g.w);
        float iw = fmaxf(rx - lx, 0.f), ih = fmaxf(ry - ly, 0.f);
        float inter = iw * ih;
        float uni = fmaxf(a1 + s_a2[m] - inter, 1e-6f);
        float iou = __fdividef(inter, uni);

        float cost = INF_COST;
        if (valid) {
            float dx = pr.x - s_cx[m], dy = pr.y - s_cy[m];
            float d2 = dx * dx + dy * dy;
            float dist = (d2 > 0.f) ? d2 * rsqrtf(d2) * rstride : 0.f;
            float soft = __exp10f(dist - 3.0f);
            float iou_cost = -3.0f * __logf(iou + 1e-7f);
            float t = s_sc[tid][s_lab[m]];
            float e = __expf(-fabsf(t));
            float r = __fdividef(1.f, 1.f + e);
            float sig = (t >= 0.f) ? r : e * r;
            float bce = fmaxf(t, 0.f) - t * iou + __logf(1.f + e);
            float sc = iou - sig;
            cost = fmaf(bce * sc, sc, iou_cost + soft);
        }
        if (inb) {
            gI[(size_t)m * NN] = iou;
            gC[(size_t)m * NN] = cost;
        }
    }
}

// Pass B: per (b,m) valid GT. Keys live in registers (no dynamic smem).
// Phase 1: top-13 iou -> dynamic_ks. Phase 2: bottom-ks cost -> atomicOr.
__global__ void __launch_bounds__(256) k_match(const float* __restrict__ pad_flag) {
    int bm = blockIdx.x;
    int b = bm / MM, m = bm % MM;
    if (pad_flag[bm] <= 0.f) return;
    int tid = threadIdx.x;
    int lane = tid & 31, wid = tid >> 5;

    __shared__ unsigned long long s_cand[8 * 13];
    __shared__ int s_ks;

    // ---- Phase 1: top-13 iou keys ----
    {
        const float* gI = g_iou + (size_t)bm * NN;
        unsigned long long k[JCNT];
        #pragma unroll
        for (int j = 0; j < JCNT; j++) {
            int n = tid + 256 * j;
            k[j] = (n < NN) ? (((unsigned long long)f2o(gI[n]) << 32) | (unsigned)n) : 0ull;
        }
        unsigned long long used = 0ull, mykey = 0ull;
        int myj = 0;
        #pragma unroll
        for (int j = 0; j < JCNT; j++)
            if (k[j] > mykey) { mykey = k[j]; myj = j; }
        for (int it = 0; it < 13; it++) {
            unsigned long long w = mykey;
            #pragma unroll
            for (int off = 16; off; off >>= 1) {
                unsigned long long o = __shfl_xor_sync(FULL, w, off);
                if (o > w) w = o;
            }
            if (mykey == w && w != 0ull) {
                used |= 1ull << myj;
                mykey = 0ull; myj = 0;
                #pragma unroll
                for (int j = 0; j < JCNT; j++)
                    if (!((used >> j) & 1ull) && k[j] > mykey) { mykey = k[j]; myj = j; }
            }
            if (lane == 0) s_cand[wid * 13 + it] = w;
        }
    }
    __syncthreads();

    if (wid == 0) {
        unsigned long long c[4];
        #pragma unroll
        for (int r = 0; r < 4; r++) {
            int i = lane + 32 * r;
            c[r] = (i < 104) ? s_cand[i] : 0ull;
        }
        int used4 = 0;
        float sum = 0.f;
        for (int it = 0; it < 13; it++) {
            unsigned long long mk = 0ull; int mr = 0;
            #pragma unroll
            for (int r = 0; r < 4; r++)
                if (!((used4 >> r) & 1) && c[r] > mk) { mk = c[r]; mr = r; }
            unsigned long long w = mk;
            #pragma unroll
            for (int off = 16; off; off >>= 1) {
                unsigned long long o = __shfl_xor_sync(FULL, w, off);
                if (o > w) w = o;
            }
            if (mk == w && w != 0ull) used4 |= 1 << mr;
            sum += __uint_as_float((unsigned)(w >> 32) ^ 0x80000000u);
        }
        int ks = (int)sum;               // trunc toward 0, matches astype(int32)
        if (ks < 1) ks = 1;
        if (ks > 13) ks = 13;
        if (lane == 0) s_ks = ks;
    }
    __syncthreads();
    int ks = s_ks;

    // ---- Phase 2: bottom-ks cost keys ----
    {
        const float* gC = g_cost + (size_t)bm * NN;
        unsigned long long k[JCNT];
        #pragma unroll
        for (int j = 0; j < JCNT; j++) {
            int n = tid + 256 * j;
            k[j] = (n < NN) ? (((unsigned long long)f2o(gC[n]) << 32) | (unsigned)n) : ~0ull;
        }
        unsigned long long used = 0ull, mykey = ~0ull;
        int myj = 0;
        #pragma unroll
        for (int j = 0; j < JCNT; j++)
            if (k[j] < mykey) { mykey = k[j]; myj = j; }
        for (int it = 0; it < ks; it++) {
            unsigned long long w = mykey;
            #pragma unroll
            for (int off = 16; off; off >>= 1) {
                unsigned long long o = __shfl_xor_sync(FULL, w, off);
                if (o < w) w = o;
            }
            if (mykey == w && w != ~0ull) {
                used |= 1ull << myj;
                mykey = ~0ull; myj = 0;
                #pragma unroll
                for (int j = 0; j < JCNT; j++)
                    if (!((used >> j) & 1ull) && k[j] < mykey) { mykey = k[j]; myj = j; }
            }
            if (lane == 0) s_cand[wid * 13 + it] = w;
        }
    }
    __syncthreads();

    if (wid == 0) {
        unsigned long long c[4];
        #pragma unroll
        for (int r = 0; r < 4; r++) {
            int i = lane + 32 * r;
            c[r] = (i < 104 && (i % 13) < ks) ? s_cand[i] : ~0ull;
        }
        int used4 = 0;
        for (int it = 0; it < ks; it++) {
            unsigned long long mk = ~0ull; int mr = 0;
            #pragma unroll
            for (int r = 0; r < 4; r++)
                if (!((used4 >> r) & 1) && c[r] < mk) { mk = c[r]; mr = r; }
            unsigned long long w = mk;
            #pragma unroll
            for (int off = 16; off; off >>= 1) {
                unsigned long long o = __shfl_xor_sync(FULL, w, off);
                if (o < w) w = o;
            }
            if (mk == w && w != ~0ull) used4 |= 1 << mr;
            if (lane == 0)
                atomicOr(&g_mask[(size_t)b * NN + (unsigned)(w & 0xFFFFFFFFu)], 1ull << m);
        }
    }
}

// Pass C: per (b, n) resolve multi-matches, emit all 4 outputs.
__global__ void k_out(const int* __restrict__ gt_labels,
                      const float* __restrict__ gt_bboxes,
                      float* __restrict__ out) {
    int idx = blockIdx.x * blockDim.x + threadIdx.x;
    if (idx >= BB * NN) return;
    int b = idx / NN, n = idx % NN;

    unsigned long long mask = g_mask[idx];
    if (__popcll(mask) > 1) {
        unsigned int bo = 0xFFFFFFFFu;
        int am = 0;
        for (int m = 0; m < MM; m++) {
            unsigned int o = f2o(g_cost[((size_t)b * MM + m) * NN + n]);
            if (o < bo) { bo = o; am = m; }
        }
        mask = 1ull << am;
    }
    bool fg = (mask != 0ull);
    int matched = fg ? (__ffsll((long long)mask) - 1) : 0;

    float lab = fg ? (float)gt_labels[b * MM + matched] : (float)CC;
    float metric = fg ? g_iou[((size_t)b * MM + matched) * NN + n] : 0.f;
    float4 bb = make_float4(0.f, 0.f, 0.f, 0.f);
    if (fg) bb = ((const float4*)gt_bboxes)[b * MM + matched];

    size_t S = (size_t)BB * NN;
    out[idx] = lab;
    out[S + idx] = 1.0f;
    ((float4*)(out + 2 * S))[idx] = bb;
    out[6 * S + idx] = metric;
}

extern "C" void kernel_launch(void* const* d_in, const int* in_sizes, int n_in,
                              void* d_out, int out_size) {
    const float* pred_bboxes = (const float*)d_in[0];
    const float* pred_scores = (const float*)d_in[1];
    const float* priors      = (const float*)d_in[2];
    const int*   gt_labels   = (const int*)d_in[3];
    const float* gt_bboxes   = (const float*)d_in[4];
    const float* pad_flag    = (const float*)d_in[5];
    float* out = (float*)d_out;

    dim3 gc(NTILES, BB);
    k_cost<<<gc, TILE>>>(pred_bboxes, pred_scores, priors,
                         gt_labels, gt_bboxes, pad_flag);

    k_match<<<BB * MM, 256>>>(pad_flag);

    k_out<<<(BB * NN + 255) / 256, 256>>>(gt_labels, gt_bboxes, out);
}

// round 5
// speedup vs baseline: 2.8586x; 1.2627x over previous
#include <cuda_runtime.h>
#include <math.h>

#define BB 32
#define MM 60
#define NN 8400
#define CC 80
#define TILE 128
#define NTILES ((NN + TILE - 1) / TILE)   // 66
#define MT 512                             // k_match threads
#define JCNT 17                            // ceil(8400/512)
#define NW (MT / 32)                       // 16 warps
#define INF_COST 1e8f
#define FULL 0xFFFFFFFFu

// Scratch (device globals: allocation-free)
__device__ float g_cost[(size_t)BB * MM * NN];               // [b][m][n]
__device__ float g_iou [(size_t)BB * MM * NN];               // [b][m][n]
__device__ unsigned long long g_mask[(size_t)BB * NN];       // per-prior GT bitmask

__device__ __forceinline__ unsigned int f2o(float f) {
    unsigned int u = __float_as_uint(f);
    return (u & 0x80000000u) ? ~u : (u | 0x80000000u);  // monotonic float->uint
}

// Pass A: per (b, prior-tile) block, 256 threads. half 0 -> m[0,30),
// half 1 -> m[30,60) for the same 128 priors. Scores+GT staged in smem.
__global__ void __launch_bounds__(2 * TILE) k_cost(
        const float* __restrict__ pred_bboxes,
        const float* __restrict__ pred_scores,
        const float* __restrict__ priors,
        const int* __restrict__ gt_labels,
        const float* __restrict__ gt_bboxes,
        const float* __restrict__ pad_flag) {
    int b = blockIdx.y;
    int n0 = blockIdx.x * TILE;
    int tid = threadIdx.x;
    int p = tid & (TILE - 1);
    int half = tid >> 7;
    int n = n0 + p;
    bool inb = (n < NN);

    __shared__ float  s_sc[TILE][CC + 1];     // stride 81: conflict-free
    __shared__ float4 s_gt[MM];
    __shared__ float  s_cx[MM], s_cy[MM], s_a2[MM], s_pf[MM];
    __shared__ int    s_lab[MM];
    __shared__ unsigned char s_v[2][TILE];

    if (tid < MM) {
        float4 g = ((const float4*)gt_bboxes)[b * MM + tid];
        s_gt[tid] = g;
        s_cx[tid] = 0.5f * (g.x + g.z);
        s_cy[tid] = 0.5f * (g.y + g.w);
        s_a2[tid] = (g.z - g.x) * (g.w - g.y);
        s_lab[tid] = gt_labels[b * MM + tid];
        s_pf[tid] = pad_flag[b * MM + tid];
    }
    {
        int rows = min(TILE, NN - n0);
        const float4* src = (const float4*)(pred_scores + ((size_t)b * NN + n0) * CC);
        int tot4 = rows * (CC / 4);
        for (int i = tid; i < tot4; i += 2 * TILE) {
            float4 v = src[i];
            int r = i / (CC / 4), c = (i % (CC / 4)) * 4;
            s_sc[r][c] = v.x; s_sc[r][c + 1] = v.y;
            s_sc[r][c + 2] = v.z; s_sc[r][c + 3] = v.w;
        }
    }
    __syncthreads();

    float4 pb = make_float4(0, 0, 0, 0), pr = make_float4(0, 0, 1, 1);
    if (inb) {
        pb = ((const float4*)pred_bboxes)[(size_t)b * NN + n];
        pr = ((const float4*)priors)[n];
        if (half == 0) g_mask[(size_t)b * NN + n] = 0ull;
    }
    float a1 = (pb.z - pb.x) * (pb.w - pb.y);
    float rstride = __frcp_rn(pr.z);

    int m0 = half * (MM / 2), m1 = m0 + MM / 2;

    // partial validity over own half of GTs -> smem, combine
    {
        bool v = false;
        #pragma unroll 5
        for (int m = m0; m < m1; m++) {
            float4 g = s_gt[m];
            float mn = fminf(fminf(pr.x - g.x, pr.y - g.y), fminf(g.z - pr.x, g.w - pr.y));
            if (mn > 0.f && s_pf[m] > 0.f) v = true;
        }
        s_v[half][p] = v ? 1 : 0;
    }
    __syncthreads();
    bool valid = s_v[0][p] | s_v[1][p];

    float* gC = g_cost + ((size_t)b * MM) * NN + n;
    float* gI = g_iou  + ((size_t)b * MM) * NN + n;

    for (int m = m0; m < m1; m++) {
        float4 g = s_gt[m];
        float lx = fmaxf(pb.x, g.x), ly = fmaxf(pb.y, g.y);
        float rx = fminf(pb.z, g.z), ry = fminf(pb.w, g.w);
        float iw = fmaxf(rx - lx, 0.f), ih = fmaxf(ry - ly, 0.f);
        float inter = iw * ih;
        float uni = fmaxf(a1 + s_a2[m] - inter, 1e-6f);
        float iou = __fdividef(inter, uni);

        float cost = INF_COST;
        if (valid) {
            float dx = pr.x - s_cx[m], dy = pr.y - s_cy[m];
            float d2 = dx * dx + dy * dy;
            float dist = (d2 > 0.f) ? d2 * rsqrtf(d2) * rstride : 0.f;
            float soft = __exp10f(dist - 3.0f);
            float iou_cost = -3.0f * __logf(iou + 1e-7f);
            float t = s_sc[p][s_lab[m]];
            float e = __expf(-fabsf(t));
            float r = __fdividef(1.f, 1.f + e);
            float sig = (t >= 0.f) ? r : e * r;
            float bce = fmaxf(t, 0.f) - t * iou + __logf(1.f + e);
            float sc = iou - sig;
            cost = fmaf(bce * sc, sc, iou_cost + soft);
        }
        if (inb) {
            gI[(size_t)m * NN] = iou;
            gC[(size_t)m * NN] = cost;
        }
    }
}

// Pass B: per (b,m) valid GT, 512 threads. Persistent keys are 32-bit ordered
// values (17 regs); full 64-bit (value||n) keys are built transiently for
// shuffles/merges so tie-breaking stays exact.
__global__ void __launch_bounds__(MT) k_match(const float* __restrict__ pad_flag) {
    int bm = blockIdx.x;
    int b = bm / MM, m = bm % MM;
    if (pad_flag[bm] <= 0.f) return;
    int tid = threadIdx.x;
    int lane = tid & 31, wid = tid >> 5;

    __shared__ unsigned long long s_cand[NW * 13];
    __shared__ int s_ks;

    // ---- Phase 1: top-13 iou (descending; need values for sum) ----
    {
        const float* gI = g_iou + (size_t)bm * NN;
        unsigned int k[JCNT];
        #pragma unroll
        for (int j = 0; j < JCNT; j++) {
            int n = tid + MT * j;
            k[j] = (n < NN) ? f2o(gI[n]) : 0u;   // sentinel 0 < f2o(0.0)=0x80000000
        }
        unsigned int used = 0, myv = 0;
        int myj = 0;
        #pragma unroll
        for (int j = 0; j < JCNT; j++)
            if (k[j] > myv) { myv = k[j]; myj = j; }
        for (int it = 0; it < 13; it++) {
            unsigned long long my = ((unsigned long long)myv << 32) | (unsigned)(tid + MT * myj);
            if (myv == 0u) my = 0ull;
            unsigned long long w = my;
            #pragma unroll
            for (int off = 16; off; off >>= 1) {
                unsigned long long o = __shfl_xor_sync(FULL, w, off);
                if (o > w) w = o;
            }
            if (my == w && w != 0ull) {           // unique winner (n embedded)
                used |= 1u << myj;
                myv = 0u; myj = 0;
                #pragma unroll
                for (int j = 0; j < JCNT; j++)
                    if (!((used >> j) & 1u) && k[j] > myv) { myv = k[j]; myj = j; }
            }
            if (lane == 0) s_cand[wid * 13 + it] = w;
        }
    }
    __syncthreads();

    // warp 0 merges NW*13 = 208 unique candidates -> dynamic_ks
    if (wid == 0) {
        unsigned long long c[7];
        #pragma unroll
        for (int r = 0; r < 7; r++) {
            int i = lane + 32 * r;
            c[r] = (i < NW * 13) ? s_cand[i] : 0ull;
        }
        int used7 = 0;
        float sum = 0.f;
        for (int it = 0; it < 13; it++) {
            unsigned long long mk = 0ull; int mr = 0;
            #pragma unroll
            for (int r = 0; r < 7; r++)
                if (!((used7 >> r) & 1) && c[r] > mk) { mk = c[r]; mr = r; }
            unsigned long long w = mk;
            #pragma unroll
            for (int off = 16; off; off >>= 1) {
                unsigned long long o = __shfl_xor_sync(FULL, w, off);
                if (o > w) w = o;
            }
            if (mk == w && w != 0ull) used7 |= 1 << mr;
            sum += __uint_as_float((unsigned)(w >> 32) ^ 0x80000000u);  // iou >= 0
        }
        int ks = (int)sum;               // trunc toward 0, matches astype(int32)
        if (ks < 1) ks = 1;
        if (ks > 13) ks = 13;
        if (lane == 0) s_ks = ks;
    }
    __syncthreads();
    int ks = s_ks;

    // ---- Phase 2: bottom-ks cost (ascending, lowest n wins ties) ----
    {
        const float* gC = g_cost + (size_t)bm * NN;
        unsigned int k[JCNT];
        #pragma unroll
        for (int j = 0; j < JCNT; j++) {
            int n = tid + MT * j;
            k[j] = (n < NN) ? f2o(gC[n]) : 0xFFFFFFFFu;  // sentinel above any real cost
        }
        unsigned int used = 0, myv = 0xFFFFFFFFu;
        int myj = 0;
        #pragma unroll
        for (int j = 0; j < JCNT; j++)
            if (k[j] < myv) { myv = k[j]; myj = j; }
        for (int it = 0; it < ks; it++) {
            unsigned long long my = ((unsigned long long)myv << 32) | (unsigned)(tid + MT * myj);
            if (myv == 0xFFFFFFFFu) my = ~0ull;
            unsigned long long w = my;
            #pragma unroll
            for (int off = 16; off; off >>= 1) {
                unsigned long long o = __shfl_xor_sync(FULL, w, off);
                if (o < w) w = o;
            }
            if (my == w && w != ~0ull) {
                used |= 1u << myj;
                myv = 0xFFFFFFFFu; myj = 0;
                #pragma unroll
                for (int j = 0; j < JCNT; j++)
                    if (!((used >> j) & 1u) && k[j] < myv) { myv = k[j]; myj = j; }
            }
            if (lane == 0) s_cand[wid * 13 + it] = w;
        }
    }
    __syncthreads();

    // warp 0 merges NW*ks candidates -> set bit m for global bottom-ks priors
    if (wid == 0) {
        unsigned long long c[7];
        #pragma unroll
        for (int r = 0; r < 7; r++) {
            int i = lane + 32 * r;
            c[r] = (i < NW * 13 && (i % 13) < ks) ? s_cand[i] : ~0ull;
        }
        int used7 = 0;
        for (int it = 0; it < ks; it++) {
            unsigned long long mk = ~0ull; int mr = 0;
            #pragma unroll
            for (int r = 0; r < 7; r++)
                if (!((used7 >> r) & 1) && c[r] < mk) { mk = c[r]; mr = r; }
            unsigned long long w = mk;
            #pragma unroll
            for (int off = 16; off; off >>= 1) {
                unsigned long long o = __shfl_xor_sync(FULL, w, off);
                if (o < w) w = o;
            }
            if (mk == w && w != ~0ull) used7 |= 1 << mr;
            if (lane == 0)
                atomicOr(&g_mask[(size_t)b * NN + (unsigned)(w & 0xFFFFFFFFu)], 1ull << m);
        }
    }
}

// Pass C: per (b, n) resolve multi-matches, emit all 4 outputs.
__global__ void k_out(const int* __restrict__ gt_labels,
                      const float* __restrict__ gt_bboxes,
                      float* __restrict__ out) {
    int idx = blockIdx.x * blockDim.x + threadIdx.x;
    if (idx >= BB * NN) return;
    int b = idx / NN, n = idx % NN;

    unsigned long long mask = g_mask[idx];
    if (__popcll(mask) > 1) {
        unsigned int bo = 0xFFFFFFFFu;
        int am = 0;
        for (int m = 0; m < MM; m++) {
            unsigned int o = f2o(g_cost[((size_t)b * MM + m) * NN + n]);
            if (o < bo) { bo = o; am = m; }
        }
        mask = 1ull << am;
    }
    bool fg = (mask != 0ull);
    int matched = fg ? (__ffsll((long long)mask) - 1) : 0;

    float lab = fg ? (float)gt_labels[b * MM + matched] : (float)CC;
    float metric = fg ? g_iou[((size_t)b * MM + matched) * NN + n] : 0.f;
    float4 bb = make_float4(0.f, 0.f, 0.f, 0.f);
    if (fg) bb = ((const float4*)gt_bboxes)[b * MM + matched];

    size_t S = (size_t)BB * NN;
    out[idx] = lab;
    out[S + idx] = 1.0f;
    ((float4*)(out + 2 * S))[idx] = bb;
    out[6 * S + idx] = metric;
}

extern "C" void kernel_launch(void* const* d_in, const int* in_sizes, int n_in,
                              void* d_out, int out_size) {
    const float* pred_bboxes = (const float*)d_in[0];
    const float* pred_scores = (const float*)d_in[1];
    const float* priors      = (const float*)d_in[2];
    const int*   gt_labels   = (const int*)d_in[3];
    const float* gt_bboxes   = (const float*)d_in[4];
    const float* pad_flag    = (const float*)d_in[5];
    float* out = (float*)d_out;

    dim3 gc(NTILES, BB);
    k_cost<<<gc, 2 * TILE>>>(pred_bboxes, pred_scores, priors,
                             gt_labels, gt_bboxes, pad_flag);

    k_match<<<BB * MM, MT>>>(pad_flag);

    k_out<<<(BB * NN + 255) / 256, 256>>>(gt_labels, gt_bboxes, out);
}